// round 17
// baseline (speedup 1.0000x reference)
#include <cuda_runtime.h>
#include <cuda_bf16.h>
#include <cstdint>

#define LSEQ 2048
typedef unsigned long long ull;

__device__ float g_ctx_scratch[2 * 16 * 2048 * 64];
__device__ uint2 g_Khi[32 * 2048 * 16];
__device__ uint2 g_Klo[32 * 2048 * 16];
__device__ uint2 g_Vhi[32 * 2048 * 16];
__device__ uint2 g_Vlo[32 * 2048 * 16];
__device__ uint2 g_Ehi[2048 * 16];        // row j = Er[2047 - j]
__device__ uint2 g_Elo[2048 * 16];

__device__ __forceinline__ uint32_t smem_u32(const void* p) {
    uint32_t a;
    asm("{ .reg .u64 t; cvta.to.shared.u64 t, %1; cvt.u32.u64 %0, t; }" : "=r"(a) : "l"(p));
    return a;
}
__device__ __forceinline__ void cpa8(uint32_t dst, const void* src) {
    asm volatile("cp.async.ca.shared.global [%0], [%1], 8;" :: "r"(dst), "l"(src));
}
#define CP_COMMIT() asm volatile("cp.async.commit_group;" ::: "memory")
#define CP_WAIT0()  asm volatile("cp.async.wait_group 0;" ::: "memory")

__device__ __forceinline__ void ldmA(uint32_t* a, uint32_t addr) {
    asm volatile("ldmatrix.sync.aligned.m8n8.x4.shared.b16 {%0,%1,%2,%3}, [%4];"
        : "=r"(a[0]), "=r"(a[1]), "=r"(a[2]), "=r"(a[3]) : "r"(addr));
}
__device__ __forceinline__ void ldmT4(uint32_t* a, uint32_t addr) {
    asm volatile("ldmatrix.sync.aligned.m8n8.x4.trans.shared.b16 {%0,%1,%2,%3}, [%4];"
        : "=r"(a[0]), "=r"(a[1]), "=r"(a[2]), "=r"(a[3]) : "r"(addr));
}
__device__ __forceinline__ void mmabf(float* d, const uint32_t* a, const uint32_t* b) {
    asm volatile("mma.sync.aligned.m16n8k16.row.col.f32.bf16.bf16.f32 "
        "{%0,%1,%2,%3}, {%4,%5,%6,%7}, {%8,%9}, {%0,%1,%2,%3};"
        : "+f"(d[0]), "+f"(d[1]), "+f"(d[2]), "+f"(d[3])
        : "r"(a[0]), "r"(a[1]), "r"(a[2]), "r"(a[3]), "r"(b[0]), "r"(b[1]));
}
__device__ __forceinline__ uint32_t pkbf(float a, float b) {
    __nv_bfloat162 h = __floats2bfloat162_rn(a, b);
    return *(uint32_t*)&h;
}
__device__ __forceinline__ void split72(char* hi, char* lo, int r, int c4, float4 v) {
    float hx = __bfloat162float(__float2bfloat16(v.x));
    float hy = __bfloat162float(__float2bfloat16(v.y));
    float hz = __bfloat162float(__float2bfloat16(v.z));
    float hw = __bfloat162float(__float2bfloat16(v.w));
    int off = r * 144 + c4 * 8;
    *(uint2*)(hi + off) = make_uint2(pkbf(v.x, v.y), pkbf(v.z, v.w));
    *(uint2*)(lo + off) = make_uint2(pkbf(v.x - hx, v.y - hy), pkbf(v.z - hz, v.w - hw));
}
__device__ __forceinline__ void split136(char* hi, char* lo, int r, int c4, float4 v) {
    float hx = __bfloat162float(__float2bfloat16(v.x));
    float hy = __bfloat162float(__float2bfloat16(v.y));
    float hz = __bfloat162float(__float2bfloat16(v.z));
    float hw = __bfloat162float(__float2bfloat16(v.w));
    int off = r * 272 + c4 * 8;
    *(uint2*)(hi + off) = make_uint2(pkbf(v.x, v.y), pkbf(v.z, v.w));
    *(uint2*)(lo + off) = make_uint2(pkbf(v.x - hx, v.y - hy), pkbf(v.z - hz, v.w - hw));
}

// ========== prep: split K/V/Er into global bf16 hi/lo (E row-reversed) =====
__global__ void prep_split(const float* __restrict__ K, const float* __restrict__ V,
                           const float* __restrict__ Er)
{
    const int m = blockIdx.x;
    const int r0 = blockIdx.y * 64;
    const float* src;
    uint2 *dhi, *dlo;
    if (m < 32)      { src = K + (size_t)m * 2048 * 64;        dhi = g_Khi + (size_t)m * 2048 * 16; dlo = g_Klo + (size_t)m * 2048 * 16; }
    else if (m < 64) { src = V + (size_t)(m - 32) * 2048 * 64; dhi = g_Vhi + (size_t)(m - 32) * 2048 * 16; dlo = g_Vlo + (size_t)(m - 32) * 2048 * 16; }
    else             { src = Er;                                dhi = g_Ehi; dlo = g_Elo; }

    for (int i = threadIdx.x; i < 1024; i += 256) {
        int r = r0 + (i >> 4), c4 = i & 15;
        int sr = (m == 64) ? (2047 - r) : r;
        float4 v = *((const float4*)(src + (size_t)sr * 64 + 4 * c4));
        float hx = __bfloat162float(__float2bfloat16(v.x));
        float hy = __bfloat162float(__float2bfloat16(v.y));
        float hz = __bfloat162float(__float2bfloat16(v.z));
        float hw = __bfloat162float(__float2bfloat16(v.w));
        dhi[(size_t)r * 16 + c4] = make_uint2(pkbf(v.x, v.y), pkbf(v.z, v.w));
        dlo[(size_t)r * 16 + c4] =
            make_uint2(pkbf(v.x - hx, v.y - hy), pkbf(v.z - hz, v.w - hw));
    }
}

// ---- smem layout ----
// score: double-buffered operands OP0/OP1 (each: KH+0 KL+9216 EH+18432 EL+27648),
//        ring at SRS (64 x 132 f32)
// pv:    PPH 0 | PPL 17408 | PVH 34816 | PVL 53248 (inside OP region)
// iz at OIZ
#define OP0 0
#define OP1 36864
#define SRS 73728
#define SRSP 132
#define PPH 0
#define PPL 17408
#define PVH 34816
#define PVL 53248
#define OIZ 107520
#define SMEM_F 107776

__global__ void __launch_bounds__(256, 2)
fused_attn(const float* __restrict__ Q, float* __restrict__ ctx, float* __restrict__ attn)
{
    extern __shared__ char sm[];
    const uint32_t sb = smem_u32(sm);
    float* Rs = (float*)(sm + SRS);
    float* smIZ = (float*)(sm + OIZ);

    const int qt = 31 - (int)blockIdx.x;
    const int bh = blockIdx.y;
    const int q0 = qt * 64;
    const int t = threadIdx.x;
    const int wid = t >> 5, lane = t & 31;
    const int wm = wid >> 1;
    const int wn = wid & 1;

    if (ctx == nullptr) ctx = g_ctx_scratch;
    const float* Qg = Q + (size_t)bh * LSEQ * 64;
    float* attng = attn + (size_t)bh * LSEQ * LSEQ;
    float* ctxg = ctx + (size_t)bh * LSEQ * 64;
    const uint2* Khi = g_Khi + (size_t)bh * 2048 * 16;
    const uint2* Klo = g_Klo + (size_t)bh * 2048 * 16;
    const uint2* Vhi = g_Vhi + (size_t)bh * 2048 * 16;
    const uint2* Vlo = g_Vlo + (size_t)bh * 2048 * 16;

    const int lr = t >> 4, lc4 = t & 15;
    const int stoff = lr * 144 + lc4 * 8;     // per-thread staging offset (row lr)

    // ================= Phase 1: scores =================
    {
        // stage Q into ring region, load A fragments
        for (int i = t; i < 1024; i += 256) {
            int r = i >> 4, c4 = i & 15;
            split72(sm + SRS, sm + SRS + 9216, r, c4,
                    *((const float4*)(Qg + (size_t)(q0 + r) * 64 + 4 * c4)));
        }
        __syncthreads();

        const int arow = (lane & 7) + 8 * ((lane >> 3) & 1);
        const int acolB = 16 * (lane >> 4);
        uint32_t AH[4][4], AL[4][4];
#pragma unroll
        for (int ks = 0; ks < 4; ks++) {
            uint32_t ro = (uint32_t)((16 * wm + arow) * 144 + ks * 32 + acolB);
            ldmA(AH[ks], sb + SRS + ro);
            ldmA(AL[ks], sb + SRS + 9216 + ro);
        }

        const int browB4 = ((lane & 7) + 8 * (lane >> 4)) * 144;
        const int bcolB = 16 * ((lane >> 3) & 1);
        float zacc[2] = {0.f, 0.f};

        // prologue: issue cp.async for tile h=0 into OP0
        {
            const int k0 = qt * 64;
            const uint32_t b = sb + OP0;
#pragma unroll
            for (int jj = 0; jj < 4; jj++) {
                size_t ki = (size_t)(k0 + lr + 16 * jj) * 16 + lc4;
                size_t ei = (size_t)(lr + 16 * jj) * 16 + lc4;
                uint32_t d = b + stoff + jj * 16 * 144;
                cpa8(d,          Khi + ki);
                cpa8(d + 9216,   Klo + ki);
                cpa8(d + 18432,  g_Ehi + ei);
                cpa8(d + 27648,  g_Elo + ei);
            }
            CP_COMMIT();
        }

        for (int h = 0; h <= qt; h++) {
            const int k0 = (qt - h) * 64;
            const uint32_t buf = sb + ((h & 1) ? OP1 : OP0);
            CP_WAIT0();
            __syncthreads();   // buf data visible; prev tile's buf^1 & ring reads done

            if (h < qt) {      // prefetch h+1 into the other buffer
                const int k0n = (qt - h - 1) * 64;
                const int e0n = 64 * (h + 1);
                const uint32_t b2 = sb + ((h & 1) ? OP0 : OP1);
#pragma unroll
                for (int jj = 0; jj < 4; jj++) {
                    size_t ki = (size_t)(k0n + lr + 16 * jj) * 16 + lc4;
                    size_t ei = (size_t)(e0n + lr + 16 * jj) * 16 + lc4;
                    uint32_t d = b2 + stoff + jj * 16 * 144;
                    cpa8(d,          Khi + ki);
                    cpa8(d + 9216,   Klo + ki);
                    cpa8(d + 18432,  g_Ehi + ei);
                    cpa8(d + 27648,  g_Elo + ei);
                }
                CP_COMMIT();
            }

            // ---- R phase (E at buf+18432/27648) ----
            const int slotW = 64 * (h & 1);
#pragma unroll
            for (int ntp = 0; ntp < 2; ntp++) {
                float racc0[4] = {0.f, 0.f, 0.f, 0.f};
                float racc1[4] = {0.f, 0.f, 0.f, 0.f};
                const uint32_t nb = (uint32_t)((32 * wn + 16 * ntp) * 144) + browB4 + bcolB;
#pragma unroll
                for (int ks = 0; ks < 4; ks++) {
                    uint32_t BH[4], BL[4];
                    ldmA(BH, buf + 18432 + nb + ks * 32);
                    ldmA(BL, buf + 27648 + nb + ks * 32);
                    mmabf(racc0, AH[ks], BH);
                    mmabf(racc0, AH[ks], BL);
                    mmabf(racc0, AL[ks], BH);
                    mmabf(racc1, AH[ks], BH + 2);
                    mmabf(racc1, AH[ks], BL + 2);
                    mmabf(racc1, AL[ks], BH + 2);
                }
                const int q = 16 * wm + (lane >> 2);
                const int c0 = slotW + 32 * wn + 16 * ntp + 2 * (lane & 3);
#pragma unroll
                for (int half = 0; half < 2; half++) {
                    float* dst = Rs + (q + 8 * half) * SRSP;
                    *((float2*)(dst + c0))     = make_float2(racc0[2 * half], racc0[2 * half + 1]);
                    *((float2*)(dst + c0 + 8)) = make_float2(racc1[2 * half], racc1[2 * half + 1]);
                }
            }
            __syncthreads();   // ring visible

            // ---- S MMA + epilogue (K at buf+0/9216) ----
            float sacc[4][4];
#pragma unroll
            for (int nt = 0; nt < 4; nt++)
#pragma unroll
                for (int r = 0; r < 4; r++) sacc[nt][r] = 0.f;
#pragma unroll
            for (int ntp = 0; ntp < 2; ntp++) {
                const uint32_t nb = (uint32_t)((32 * wn + 16 * ntp) * 144) + browB4 + bcolB;
#pragma unroll
                for (int ks = 0; ks < 4; ks++) {
                    uint32_t BH[4], BL[4];
                    ldmA(BH, buf + nb + ks * 32);
                    ldmA(BL, buf + 9216 + nb + ks * 32);
                    mmabf(sacc[2 * ntp], AH[ks], BH);
                    mmabf(sacc[2 * ntp], AH[ks], BL);
                    mmabf(sacc[2 * ntp], AL[ks], BH);
                    mmabf(sacc[2 * ntp + 1], AH[ks], BH + 2);
                    mmabf(sacc[2 * ntp + 1], AH[ks], BL + 2);
                    mmabf(sacc[2 * ntp + 1], AL[ks], BH + 2);
                }
            }
            const int s0 = 64 * (h & 1);
            const int s1 = 64 * ((h + 1) & 1);
            const bool diag = (h == 0);
#pragma unroll
            for (int nt = 0; nt < 4; nt++) {
                const int klocal = 32 * wn + ((nt & 1) ? 8 : 0) + 16 * (nt >> 1) + 2 * (lane & 3);
                const int kg = k0 + klocal;
                const int si = (nt >> 1) * 2 + (nt & 1);
#pragma unroll
                for (int rh = 0; rh < 2; rh++) {
                    const int r = 16 * wm + 8 * rh + (lane >> 2);
                    const int qg = q0 + r;
                    const int d0 = r - klocal;
                    const int d1 = d0 - 1;
                    float r0 = Rs[r * SRSP + ((d0 & 63) + (d0 >= 0 ? s0 : s1))];
                    float r1 = Rs[r * SRSP + ((d1 & 63) + (d1 >= 0 ? s0 : s1))];
                    float sv0 = (sacc[si][2 * rh] + r0) * 0.125f;
                    float sv1 = (sacc[si][2 * rh + 1] + r1) * 0.125f;
                    float p0 = __expf(sv0), p1 = __expf(sv1);
                    if (diag) {
                        if (kg > qg) p0 = 0.f;
                        if (kg + 1 > qg) p1 = 0.f;
                    }
                    zacc[rh] += p0 + p1;
                    *((float2*)(attng + (size_t)qg * LSEQ + kg)) = make_float2(p0, p1);
                }
            }
        }

        // z reduce -> smem iz
#pragma unroll
        for (int rh = 0; rh < 2; rh++) {
            float v = zacc[rh];
            v += __shfl_xor_sync(0xffffffffu, v, 1);
            v += __shfl_xor_sync(0xffffffffu, v, 2);
            zacc[rh] = v;
        }
        __syncthreads();
        float* zb = Rs;
        if ((lane & 3) == 0) {
#pragma unroll
            for (int rh = 0; rh < 2; rh++) {
                int row = 16 * wm + 8 * rh + (lane >> 2);
                zb[row * 2 + wn] = zacc[rh];
            }
        }
        __syncthreads();
        if (t < 64)
            smIZ[t] = 1.f / (zb[2 * t] + zb[2 * t + 1]);
        __syncthreads();
    }

    // ================= Phase 2: normalize + PV =================
    {
        float cacc[4][4];
#pragma unroll
        for (int nt = 0; nt < 4; nt++)
#pragma unroll
            for (int r = 0; r < 4; r++) cacc[nt][r] = 0.f;

        const int arow = (lane & 7) + 8 * ((lane >> 3) & 1);
        const int acolB = 16 * (lane >> 4);
        const int btrow4 = (lane & 15) * 144 + (lane >> 4) * 16;
        const int bncol = (32 * wn) * 2;

        const int vr = t >> 4, vc4 = t & 15;
        const int pr = t >> 5, pc4 = t & 31;

        const int kcov = (qt + 1) * 64;
        const int ktmax = qt >> 1;
        for (int kt = 0; kt <= ktmax; kt++) {
            const int k0 = kt * 128;
            const bool oob = (k0 + 4 * pc4) >= kcov;
            __syncthreads();          // V/P smem free (prev MMA done)

            // V staging via cp.async (overlaps with P processing below)
#pragma unroll
            for (int jj = 0; jj < 8; jj++) {
                size_t vi = (size_t)(k0 + vr + 16 * jj) * 16 + vc4;
                uint32_t d = sb + PVH + (vr + 16 * jj) * 144 + vc4 * 8;
                cpa8(d, Vhi + vi);
                cpa8(d + (PVL - PVH), Vlo + vi);
            }
            CP_COMMIT();

            float4 pbuf[8];
#pragma unroll
            for (int jj = 0; jj < 8; jj++)
                pbuf[jj] = *((const float4*)(attng +
                    (size_t)(q0 + pr + 8 * jj) * LSEQ + k0 + 4 * pc4));
#pragma unroll
            for (int jj = 0; jj < 8; jj++) {
                int r = pr + 8 * jj;
                float iz = smIZ[r];
                float4 pv = pbuf[jj];
                pv.x *= iz; pv.y *= iz; pv.z *= iz; pv.w *= iz;
                if (oob) pv = make_float4(0.f, 0.f, 0.f, 0.f);
                *((float4*)(attng + (size_t)(q0 + r) * LSEQ + k0 + 4 * pc4)) = pv;
                split136(sm + PPH, sm + PPL, r, pc4, pv);
            }
            CP_WAIT0();
            __syncthreads();

#pragma unroll 2
            for (int ks = 0; ks < 8; ks++) {
                uint32_t PH[4], PL[4];
                {
                    uint32_t ro = (uint32_t)((16 * wm + arow) * 272 + ks * 32 + acolB);
                    ldmA(PH, sb + PPH + ro);
                    ldmA(PL, sb + PPL + ro);
                }
#pragma unroll
                for (int ntp = 0; ntp < 2; ntp++) {
                    uint32_t BH[4], BL[4];
                    uint32_t bo = (uint32_t)(16 * ks * 144) + btrow4 + bncol + ntp * 32;
                    ldmT4(BH, sb + PVH + bo);
                    ldmT4(BL, sb + PVL + bo);
                    mmabf(cacc[2 * ntp], PH, BH);
                    mmabf(cacc[2 * ntp], PH, BL);
                    mmabf(cacc[2 * ntp], PL, BH);
                    mmabf(cacc[2 * ntp + 1], PH, BH + 2);
                    mmabf(cacc[2 * ntp + 1], PH, BL + 2);
                    mmabf(cacc[2 * ntp + 1], PL, BH + 2);
                }
            }
        }

        const int kend = (ktmax + 1) * 128;
        const int nz = (LSEQ - kend) >> 2;
        if (nz > 0) {
            const float4 z4 = make_float4(0.f, 0.f, 0.f, 0.f);
            for (int i = t; i < 64 * nz; i += 256) {
                int r = i / nz, c = i - r * nz;
                *((float4*)(attng + (size_t)(q0 + r) * LSEQ + kend + 4 * c)) = z4;
            }
        }

#pragma unroll
        for (int nt = 0; nt < 4; nt++)
#pragma unroll
            for (int rh = 0; rh < 2; rh++) {
                int q = q0 + 16 * wm + 8 * rh + (lane >> 2);
                int d = 32 * wn + 16 * (nt >> 1) + 8 * (nt & 1) + 2 * (lane & 3);
                *((float2*)(ctxg + (size_t)q * 64 + d)) =
                    make_float2(cacc[nt][2 * rh], cacc[nt][2 * rh + 1]);
            }
    }
}

extern "C" void kernel_launch(void* const* d_in, const int* in_sizes, int n_in,
                              void* d_out, int out_size) {
    const float* Q  = (const float*)d_in[0];
    const float* K  = (const float*)d_in[1];
    const float* V  = (const float*)d_in[2];
    const float* Er = (const float*)d_in[4];

    const long long CTXN = (long long)2 * 16 * 2048 * 64;
    const long long ATTN = (long long)2 * 16 * 2048 * 2048;
    float* out = (float*)d_out;
    float* ctx; float* attn;
    if ((long long)out_size >= CTXN + ATTN) { ctx = out; attn = out + CTXN; }
    else if ((long long)out_size == ATTN)   { ctx = nullptr; attn = out; }
    else                                    { ctx = out; attn = out; }

    prep_split<<<dim3(65, 32), 256>>>(K, V, Er);

    cudaFuncSetAttribute(fused_attn, cudaFuncAttributeMaxDynamicSharedMemorySize, SMEM_F);
    fused_attn<<<dim3(32, 32), 256, SMEM_F>>>(Q, ctx, attn);
}